// round 1
// baseline (speedup 1.0000x reference)
#include <cuda_runtime.h>
#include <math.h>

#define HSZ 1024
#define NHD 16
#define HDM 64
#define SEQ 2048
#define BSZ 2
#define NROWS (BSZ*SEQ)         /* 4096 */
#define NSTAT (BSZ*NHD*SEQ)     /* 65536 */

// -------- scratch (device globals; no allocations allowed) -----------------
__device__ float g_Q [NROWS*HSZ];
__device__ float g_K [NROWS*HSZ];
__device__ float g_V [NROWS*HSZ];
__device__ float g_GK[NROWS*HSZ];
__device__ float g_GQ[BSZ*HSZ];
__device__ float g_gov[NSTAT];
__device__ float g_ent[NSTAT];
__device__ float g_mxp[NSTAT];

// ===========================================================================
// Projection GEMM: out = X[4096,1024] @ W[1024,1024] + b, for 4 matrices.
// 64x64 tile, BK=16, 256 threads, 4x4 register tile, float4 smem reads.
// ===========================================================================
__global__ __launch_bounds__(256) void proj_kernel(
    const float* __restrict__ X,
    const float* __restrict__ Wq, const float* __restrict__ bq,
    const float* __restrict__ Wk, const float* __restrict__ bk,
    const float* __restrict__ Wv, const float* __restrict__ bv,
    const float* __restrict__ Wg, const float* __restrict__ bg)
{
    __shared__ float As[16][68];   // [kk][i], padded: 2-way max on transpose store
    __shared__ float Bs[16][68];   // [kk][j]

    const float* W; const float* bias; float* out;
    switch (blockIdx.z) {
        case 0:  W = Wq; bias = bq; out = g_Q;  break;
        case 1:  W = Wk; bias = bk; out = g_K;  break;
        case 2:  W = Wv; bias = bv; out = g_V;  break;
        default: W = Wg; bias = bg; out = g_GK; break;
    }

    const int t  = threadIdx.x;
    const int ty = t >> 4, tx = t & 15;
    const int r0 = blockIdx.y * 64, c0 = blockIdx.x * 64;

    float acc[4][4];
#pragma unroll
    for (int r = 0; r < 4; r++)
#pragma unroll
        for (int c = 0; c < 4; c++) acc[r][c] = 0.f;

    const int ia = t >> 4, ka = t & 15;   // A-load mapping
    const int kb = t >> 6, jb = t & 63;   // B-load mapping

    for (int k0 = 0; k0 < HSZ; k0 += 16) {
#pragma unroll
        for (int w = 0; w < 4; w++)
            As[ka][ia + 16*w] = X[(size_t)(r0 + ia + 16*w)*HSZ + k0 + ka];
#pragma unroll
        for (int w = 0; w < 4; w++)
            Bs[kb + 4*w][jb] = W[(size_t)(k0 + kb + 4*w)*HSZ + c0 + jb];
        __syncthreads();

#pragma unroll
        for (int kk = 0; kk < 16; kk++) {
            float4 a4 = *(const float4*)&As[kk][ty*4];
            float4 b4 = *(const float4*)&Bs[kk][tx*4];
            float ar[4] = {a4.x, a4.y, a4.z, a4.w};
            float br[4] = {b4.x, b4.y, b4.z, b4.w};
#pragma unroll
            for (int r = 0; r < 4; r++)
#pragma unroll
                for (int c = 0; c < 4; c++)
                    acc[r][c] += ar[r]*br[c];
        }
        __syncthreads();
    }

    float4 bb = *(const float4*)&bias[c0 + tx*4];
#pragma unroll
    for (int r = 0; r < 4; r++) {
        float4 o;
        o.x = acc[r][0] + bb.x; o.y = acc[r][1] + bb.y;
        o.z = acc[r][2] + bb.z; o.w = acc[r][3] + bb.w;
        *(float4*)&out[(size_t)(r0 + ty*4 + r)*HSZ + c0 + tx*4] = o;
    }
}

// ===========================================================================
// gq = governance_embeddings[2,1024] @ Wgq + bgq
// ===========================================================================
__global__ void gq_kernel(const float* __restrict__ ge,
                          const float* __restrict__ W,
                          const float* __restrict__ bias)
{
    int c = blockIdx.x * blockDim.x + threadIdx.x;  // 0..1023
    int r = blockIdx.y;                              // 0..1
    const float* g = ge + (size_t)r * HSZ;
    float a0 = 0.f, a1 = 0.f, a2 = 0.f, a3 = 0.f;
    for (int k = 0; k < HSZ; k += 4) {
        a0 += g[k+0] * W[(size_t)(k+0)*HSZ + c];
        a1 += g[k+1] * W[(size_t)(k+1)*HSZ + c];
        a2 += g[k+2] * W[(size_t)(k+2)*HSZ + c];
        a3 += g[k+3] * W[(size_t)(k+3)*HSZ + c];
    }
    g_GQ[(size_t)r*HSZ + c] = (a0+a1) + (a2+a3) + bias[c];
}

// ===========================================================================
// gov_scores[b,h,s] = sum_d gq[b,h,d] * gk[b,s,h,d].  One warp per output.
// ===========================================================================
__global__ void gov_kernel()
{
    int gw   = (blockIdx.x * blockDim.x + threadIdx.x) >> 5;
    int lane = threadIdx.x & 31;
    if (gw >= NSTAT) return;
    int s  = gw & (SEQ-1);
    int bh = gw >> 11;
    int b = bh >> 4, h = bh & 15;
    const float* gq = g_GQ + (size_t)b*HSZ + h*HDM;
    const float* gk = g_GK + ((size_t)(b*SEQ + s))*HSZ + h*HDM;
    float acc = gq[lane]*gk[lane] + gq[lane+32]*gk[lane+32];
#pragma unroll
    for (int o = 16; o; o >>= 1)
        acc += __shfl_xor_sync(0xffffffffu, acc, o);
    if (lane == 0) g_gov[gw] = acc;
}

// ===========================================================================
// Flash attention (fp32), 64 query rows x 64 key cols per tile.
// Tracks per-row: m (max), Z (denom), T = sum e*(s-m) (entropy), E (max e).
// Score phase cols {tx+16e} (conflict-free swizzled K float4 reads);
// O phase cols {4tx+c} (vector V reads), bridged via P in smem (aliases K).
// ===========================================================================
__global__ __launch_bounds__(256) void attn_kernel(float* __restrict__ ctx)
{
    __shared__ float qs[64*64];
    __shared__ float ks[64*64];   // aliased as P tile after score phase
    __shared__ float vs[64*64];

    const int t  = threadIdx.x;
    const int ty = t >> 4, tx = t & 15;
    const int bh = blockIdx.y;
    const int b = bh >> 4, h = bh & 15;
    const int q0 = blockIdx.x * 64;
    const int i0 = ty * 4;

    const float* Qg = g_Q + ((size_t)(b*SEQ + q0))*HSZ + h*HDM;
    const float* Kg = g_K + ((size_t)(b*SEQ))*HSZ + h*HDM;
    const float* Vg = g_V + ((size_t)(b*SEQ))*HSZ + h*HDM;

    for (int l = t; l < 4096; l += 256) {
        int i = l >> 6, d = l & 63;
        qs[i*64 + d] = Qg[(size_t)i*HSZ + d];
    }

    float O[4][4];
    float m[4], Z[4], T[4], E[4];
#pragma unroll
    for (int r = 0; r < 4; r++) {
        m[r] = -1e30f; Z[r] = 0.f; T[r] = 0.f; E[r] = 0.f;
#pragma unroll
        for (int c = 0; c < 4; c++) O[r][c] = 0.f;
    }

    const int ksw = (tx & 7) << 2;

    for (int j0 = 0; j0 < SEQ; j0 += 64) {
        __syncthreads();
        for (int l = t; l < 4096; l += 256) {
            int j = l >> 6, d = l & 63;
            ks[j*64 + (d ^ ((j & 7) << 2))] = Kg[(size_t)(j0+j)*HSZ + d];
            vs[j*64 + d]                    = Vg[(size_t)(j0+j)*HSZ + d];
        }
        __syncthreads();

        // ---- scores: s[r][e] = q_{i0+r} . k_{tx+16e} ----
        float s[4][4];
#pragma unroll
        for (int r = 0; r < 4; r++)
#pragma unroll
            for (int e = 0; e < 4; e++) s[r][e] = 0.f;

#pragma unroll
        for (int d4 = 0; d4 < 16; d4++) {
            float4 q4[4];
#pragma unroll
            for (int r = 0; r < 4; r++)
                q4[r] = *(const float4*)&qs[(i0+r)*64 + d4*4];
            const int kc = (d4*4) ^ ksw;
#pragma unroll
            for (int e = 0; e < 4; e++) {
                float4 k4 = *(const float4*)&ks[(tx + 16*e)*64 + kc];
#pragma unroll
                for (int r = 0; r < 4; r++) {
                    s[r][e] += q4[r].x*k4.x;
                    s[r][e] += q4[r].y*k4.y;
                    s[r][e] += q4[r].z*k4.z;
                    s[r][e] += q4[r].w*k4.w;
                }
            }
        }

        // ---- online softmax update (per row; all 16 tx lanes replicate) ----
#pragma unroll
        for (int r = 0; r < 4; r++) {
#pragma unroll
            for (int e = 0; e < 4; e++) s[r][e] *= 0.125f;
            float lm = fmaxf(fmaxf(s[r][0], s[r][1]), fmaxf(s[r][2], s[r][3]));
#pragma unroll
            for (int o = 8; o; o >>= 1)
                lm = fmaxf(lm, __shfl_xor_sync(0xffffffffu, lm, o, 16));
            float mo = m[r];
            float mn = fmaxf(mo, lm);
            float al = __expf(mo - mn);
            float Zo = Z[r];
            T[r] = al * (T[r] + (mo - mn) * Zo);
            Z[r] = al * Zo;
            E[r] *= al;
            O[r][0] *= al; O[r][1] *= al; O[r][2] *= al; O[r][3] *= al;
            m[r] = mn;

            float sp = 0.f, st = 0.f, pm = 0.f;
#pragma unroll
            for (int e = 0; e < 4; e++) {
                float dd = s[r][e] - mn;
                float p  = __expf(dd);
                sp += p; st += p * dd; pm = fmaxf(pm, p);
                s[r][e] = p;
            }
#pragma unroll
            for (int o = 8; o; o >>= 1) {
                sp += __shfl_xor_sync(0xffffffffu, sp, o, 16);
                st += __shfl_xor_sync(0xffffffffu, st, o, 16);
                pm  = fmaxf(pm, __shfl_xor_sync(0xffffffffu, pm, o, 16));
            }
            Z[r] += sp; T[r] += st; E[r] = fmaxf(E[r], pm);
        }

        __syncthreads();                 // everyone done reading ks
        float* ps = ks;                  // alias K tile as P tile
#pragma unroll
        for (int r = 0; r < 4; r++)
#pragma unroll
            for (int e = 0; e < 4; e++)
                ps[(i0+r)*64 + (tx + 16*e)] = s[r][e];
        __syncthreads();                 // P visible

        // ---- O += P @ V ----
#pragma unroll
        for (int jj = 0; jj < 16; jj++) {
            float pr[4][4];
#pragma unroll
            for (int r = 0; r < 4; r++) {
                float4 p4 = *(const float4*)&ps[(i0+r)*64 + jj*4];
                pr[r][0] = p4.x; pr[r][1] = p4.y; pr[r][2] = p4.z; pr[r][3] = p4.w;
            }
#pragma unroll
            for (int u = 0; u < 4; u++) {
                float4 v4 = *(const float4*)&vs[(jj*4 + u)*64 + tx*4];
#pragma unroll
                for (int r = 0; r < 4; r++) {
                    O[r][0] += pr[r][u]*v4.x;
                    O[r][1] += pr[r][u]*v4.y;
                    O[r][2] += pr[r][u]*v4.z;
                    O[r][3] += pr[r][u]*v4.w;
                }
            }
        }
    }

    // ---- epilogue: normalize, write context + per-row stats ----
#pragma unroll
    for (int r = 0; r < 4; r++) {
        float inv = 1.0f / Z[r];
        float4 o4;
        o4.x = O[r][0]*inv; o4.y = O[r][1]*inv;
        o4.z = O[r][2]*inv; o4.w = O[r][3]*inv;
        int row = q0 + i0 + r;
        *(float4*)&ctx[((size_t)(b*SEQ + row))*HSZ + h*HDM + tx*4] = o4;
        if (tx == 0) {
            int idx = bh*SEQ + row;
            g_ent[idx] = logf(Z[r]) - T[r]*inv;
            g_mxp[idx] = E[r]*inv;
        }
    }
}

// ===========================================================================
// Deterministic final reduction: 3 scalar means (no atomics).
// ===========================================================================
__global__ void reduce_kernel(float* __restrict__ out, int n_ctx)
{
    __shared__ float se[512], si[512], sc[512];
    int t = threadIdx.x;
    float e = 0.f, i = 0.f, c = 0.f;
    for (int l = t; l < NSTAT; l += 512) {
        e += g_ent[l];
        i += fabsf(g_gov[l]);
        c += g_mxp[l];
    }
    se[t] = e; si[t] = i; sc[t] = c;
    __syncthreads();
    for (int s2 = 256; s2 > 0; s2 >>= 1) {
        if (t < s2) { se[t] += se[t+s2]; si[t] += si[t+s2]; sc[t] += sc[t+s2]; }
        __syncthreads();
    }
    if (t == 0) {
        const float inv = 1.0f / (float)NSTAT;
        out[n_ctx + 0] = se[0] * inv;   // entropy
        out[n_ctx + 1] = si[0] * inv;   // influence
        out[n_ctx + 2] = sc[0] * inv;   // concentration
    }
}

// ===========================================================================
extern "C" void kernel_launch(void* const* d_in, const int* in_sizes, int n_in,
                              void* d_out, int out_size)
{
    const float* X   = (const float*)d_in[0];
    const float* GE  = (const float*)d_in[1];
    const float* Wq  = (const float*)d_in[2];  const float* bq  = (const float*)d_in[3];
    const float* Wk  = (const float*)d_in[4];  const float* bk  = (const float*)d_in[5];
    const float* Wv  = (const float*)d_in[6];  const float* bv  = (const float*)d_in[7];
    const float* Wgq = (const float*)d_in[8];  const float* bgq = (const float*)d_in[9];
    const float* Wgk = (const float*)d_in[10]; const float* bgk = (const float*)d_in[11];
    float* out = (float*)d_out;

    proj_kernel<<<dim3(16, 64, 4), 256>>>(X, Wq, bq, Wk, bk, Wv, bv, Wgk, bgk);
    gq_kernel<<<dim3(4, 2), 256>>>(GE, Wgq, bgq);
    gov_kernel<<<NSTAT*32/256, 256>>>();
    attn_kernel<<<dim3(SEQ/64, BSZ*NHD), 256>>>(out);
    reduce_kernel<<<1, 512>>>(out, out_size - 3);
}

// round 2
// speedup vs baseline: 2.6461x; 2.6461x over previous
#include <cuda_runtime.h>
#include <math.h>
#include <stdint.h>

#define HSZ 1024
#define NHD 16
#define HDM 64
#define SEQ 2048
#define BSZ 2
#define NROWS (BSZ*SEQ)         /* 4096 */
#define NSTAT (BSZ*NHD*SEQ)     /* 65536 */

// -------- scratch (device globals; no allocations allowed) -----------------
__device__ float g_Q [NROWS*HSZ];
__device__ float g_K [NROWS*HSZ];
__device__ float g_V [NROWS*HSZ];
__device__ float g_GK[NROWS*HSZ];
__device__ float g_GQ[BSZ*HSZ];
__device__ float g_gov[NSTAT];
__device__ float g_ent[NSTAT];
__device__ float g_mxp[NSTAT];

// -------- tf32 helpers ------------------------------------------------------
__device__ __forceinline__ float f2tf(float x){
    uint32_t u; asm("cvt.rna.tf32.f32 %0, %1;" : "=r"(u) : "f"(x));
    return __uint_as_float(u);
}
__device__ __forceinline__ void mma8(float c[4], const uint32_t a[4], const uint32_t b[2]){
    asm volatile("mma.sync.aligned.m16n8k8.row.col.f32.tf32.tf32.f32 "
        "{%0,%1,%2,%3}, {%4,%5,%6,%7}, {%8,%9}, {%0,%1,%2,%3};"
        : "+f"(c[0]), "+f"(c[1]), "+f"(c[2]), "+f"(c[3])
        : "r"(a[0]), "r"(a[1]), "r"(a[2]), "r"(a[3]), "r"(b[0]), "r"(b[1]));
}
// permute k within 8-groups so (k, k+4) are adjacent -> LDS.64 fragment loads
__device__ __forceinline__ int pe(int e){ return ((e&3)<<1) | ((e>>2)&1); }

// ===========================================================================
// Projection GEMM (tf32 tensor cores):
// out = X[4096,1024] @ W[1024,1024] + b for Q/K/V/GK (z selects matrix).
// CTA tile 128x128, BK=32, 8 warps each 32x64 (2 m-tiles x 8 n-tiles).
// ===========================================================================
#define PLA 40    /* As row stride (floats); 40 mod 32 == 8 -> conflict-free */
#define PLB 136   /* Bs row stride; 136 mod 32 == 8 -> conflict-free */

__global__ __launch_bounds__(256) void proj_kernel(
    const float* __restrict__ X,
    const float* __restrict__ Wq, const float* __restrict__ bq,
    const float* __restrict__ Wk, const float* __restrict__ bk,
    const float* __restrict__ Wv, const float* __restrict__ bv,
    const float* __restrict__ Wg, const float* __restrict__ bg)
{
    __shared__ float As[128*PLA];   // 20.5 KB, k-permuted
    __shared__ float Bs[32*PLB];    // 17.4 KB, [k][n] natural

    const float* W; const float* bias; float* out;
    switch (blockIdx.z) {
        case 0:  W = Wq; bias = bq; out = g_Q;  break;
        case 1:  W = Wk; bias = bk; out = g_K;  break;
        case 2:  W = Wv; bias = bv; out = g_V;  break;
        default: W = Wg; bias = bg; out = g_GK; break;
    }

    const int t = threadIdx.x;
    const int lane = t & 31, warp = t >> 5;
    const int qr = lane >> 2, qc = lane & 3;
    const int wm = warp >> 1, wn = warp & 1;
    const int r0 = blockIdx.y * 128, c0 = blockIdx.x * 128;

    float acc[2][8][4];
#pragma unroll
    for (int mt = 0; mt < 2; mt++)
#pragma unroll
        for (int nt = 0; nt < 8; nt++)
#pragma unroll
            for (int k = 0; k < 4; k++) acc[mt][nt][k] = 0.f;

    for (int k0 = 0; k0 < HSZ; k0 += 32) {
#pragma unroll
        for (int i = 0; i < 4; i++) {
            int idx = t + i*256;
            int r = idx >> 3, c = (idx & 7) << 2;
            float4 v = *(const float4*)&X[(size_t)(r0+r)*HSZ + k0 + c];
            float* p = &As[r*PLA + (c & ~7)];
            int e = c & 7;
            p[pe(e+0)] = f2tf(v.x); p[pe(e+1)] = f2tf(v.y);
            p[pe(e+2)] = f2tf(v.z); p[pe(e+3)] = f2tf(v.w);
        }
#pragma unroll
        for (int i = 0; i < 4; i++) {
            int idx = t + i*256;
            int r = idx >> 5, c = (idx & 31) << 2;
            float4 v = *(const float4*)&W[(size_t)(k0+r)*HSZ + c0 + c];
            float4 o = make_float4(f2tf(v.x), f2tf(v.y), f2tf(v.z), f2tf(v.w));
            *(float4*)&Bs[r*PLB + c] = o;
        }
        __syncthreads();

#pragma unroll
        for (int u = 0; u < 4; u++) {
            uint32_t af[2][4];
#pragma unroll
            for (int mt = 0; mt < 2; mt++) {
                int rm = wm*32 + mt*16;
                float2 lo = *(const float2*)&As[(rm+qr  )*PLA + u*8 + 2*qc];
                float2 hi = *(const float2*)&As[(rm+qr+8)*PLA + u*8 + 2*qc];
                af[mt][0] = __float_as_uint(lo.x); af[mt][1] = __float_as_uint(hi.x);
                af[mt][2] = __float_as_uint(lo.y); af[mt][3] = __float_as_uint(hi.y);
            }
#pragma unroll
            for (int nt = 0; nt < 8; nt++) {
                int col = wn*64 + nt*8 + qr;
                uint32_t bb[2];
                bb[0] = __float_as_uint(Bs[(u*8+qc  )*PLB + col]);
                bb[1] = __float_as_uint(Bs[(u*8+qc+4)*PLB + col]);
                mma8(acc[0][nt], af[0], bb);
                mma8(acc[1][nt], af[1], bb);
            }
        }
        __syncthreads();
    }

#pragma unroll
    for (int mt = 0; mt < 2; mt++) {
        int rm = r0 + wm*32 + mt*16;
#pragma unroll
        for (int nt = 0; nt < 8; nt++) {
            int col = c0 + wn*64 + nt*8 + 2*qc;
            float b0 = bias[col], b1 = bias[col+1];
            float2 o;
            o.x = acc[mt][nt][0] + b0; o.y = acc[mt][nt][1] + b1;
            *(float2*)&out[(size_t)(rm+qr)*HSZ + col] = o;
            o.x = acc[mt][nt][2] + b0; o.y = acc[mt][nt][3] + b1;
            *(float2*)&out[(size_t)(rm+qr+8)*HSZ + col] = o;
        }
    }
}

// ===========================================================================
// gq = governance_embeddings[2,1024] @ Wgq + bgq   (tiny, SIMT)
// ===========================================================================
__global__ void gq_kernel(const float* __restrict__ ge,
                          const float* __restrict__ W,
                          const float* __restrict__ bias)
{
    int c = blockIdx.x * blockDim.x + threadIdx.x;
    int r = blockIdx.y;
    const float* g = ge + (size_t)r * HSZ;
    float a0 = 0.f, a1 = 0.f, a2 = 0.f, a3 = 0.f;
    for (int k = 0; k < HSZ; k += 4) {
        a0 += g[k+0] * W[(size_t)(k+0)*HSZ + c];
        a1 += g[k+1] * W[(size_t)(k+1)*HSZ + c];
        a2 += g[k+2] * W[(size_t)(k+2)*HSZ + c];
        a3 += g[k+3] * W[(size_t)(k+3)*HSZ + c];
    }
    g_GQ[(size_t)r*HSZ + c] = (a0+a1) + (a2+a3) + bias[c];
}

// ===========================================================================
// gov_scores[b,h,s] = sum_d gq[b,h,d]*gk[b,s,h,d]. One warp per output.
// ===========================================================================
__global__ void gov_kernel()
{
    int gw   = (blockIdx.x * blockDim.x + threadIdx.x) >> 5;
    int lane = threadIdx.x & 31;
    if (gw >= NSTAT) return;
    int s  = gw & (SEQ-1);
    int bh = gw >> 11;
    int b = bh >> 4, h = bh & 15;
    const float* gq = g_GQ + (size_t)b*HSZ + h*HDM;
    const float* gk = g_GK + ((size_t)(b*SEQ + s))*HSZ + h*HDM;
    float acc = gq[lane]*gk[lane] + gq[lane+32]*gk[lane+32];
#pragma unroll
    for (int o = 16; o; o >>= 1)
        acc += __shfl_xor_sync(0xffffffffu, acc, o);
    if (lane == 0) g_gov[gw] = acc;
}

// ===========================================================================
// Flash attention on tf32 tensor cores.
// CTA: 128 q-rows x (j-tiles of 64), 4 warps each own 32 rows x full width.
// S=QK^T and O+=PV via m16n8k8 mma; P bridged through smem (tf32).
// Online stats per row: m, Z, T=sum p*(s-m), E=max p.
// ===========================================================================
#define ALD 72   /* 72 mod 32 == 8 -> conflict-free fragment loads */
#define QS_OFF 0
#define KS_OFF (128*ALD)
#define VS_OFF (KS_OFF + 64*ALD)
#define PS_OFF (VS_OFF + 64*ALD)
#define ATT_SMEM ((PS_OFF + 128*ALD)*4)   /* 110592 bytes */

__global__ __launch_bounds__(128) void attn_kernel(float* __restrict__ ctx)
{
    extern __shared__ float sm[];
    float* qs = sm + QS_OFF;   // 128 x 64, k-permuted
    float* ks = sm + KS_OFF;   // 64 x 64, k-permuted
    float* vs = sm + VS_OFF;   // 64 x 64, natural [j][d]
    float* ps = sm + PS_OFF;   // 128 x 64 probs, j-permuted

    const int t = threadIdx.x;
    const int lane = t & 31, warp = t >> 5;
    const int qr = lane >> 2, qc = lane & 3;
    const int bh = blockIdx.y, b = bh >> 4, h = bh & 15;
    const int q0 = blockIdx.x * 128;
    const int wr = warp * 32;

    const float* Qg = g_Q + ((size_t)(b*SEQ + q0))*HSZ + h*HDM;
    const float* Kg = g_K + ((size_t)(b*SEQ))*HSZ + h*HDM;
    const float* Vg = g_V + ((size_t)(b*SEQ))*HSZ + h*HDM;

    // stage Q (coalesced, tf32, permuted)
    for (int idx = t; idx < 2048; idx += 128) {
        int r = idx >> 4, c = (idx & 15) << 2;
        float4 v = *(const float4*)&Qg[(size_t)r*HSZ + c];
        float* p = &qs[r*ALD + (c & ~7)];
        int e = c & 7;
        p[pe(e+0)] = f2tf(v.x); p[pe(e+1)] = f2tf(v.y);
        p[pe(e+2)] = f2tf(v.z); p[pe(e+3)] = f2tf(v.w);
    }

    float O[2][8][4];
    float m[2][2], Z[2][2], T[2][2], E[2][2];
#pragma unroll
    for (int mt = 0; mt < 2; mt++) {
#pragma unroll
        for (int hi = 0; hi < 2; hi++) {
            m[mt][hi] = -1e30f; Z[mt][hi] = 0.f; T[mt][hi] = 0.f; E[mt][hi] = 0.f;
        }
#pragma unroll
        for (int nt = 0; nt < 8; nt++)
#pragma unroll
            for (int k = 0; k < 4; k++) O[mt][nt][k] = 0.f;
    }

    for (int j0 = 0; j0 < SEQ; j0 += 64) {
        __syncthreads();   // prior tile's reads of ks/vs/ps complete (also covers Q stage)
        for (int idx = t; idx < 1024; idx += 128) {
            int r = idx >> 4, c = (idx & 15) << 2;
            float4 kv = *(const float4*)&Kg[(size_t)(j0+r)*HSZ + c];
            float* p = &ks[r*ALD + (c & ~7)];
            int e = c & 7;
            p[pe(e+0)] = f2tf(kv.x); p[pe(e+1)] = f2tf(kv.y);
            p[pe(e+2)] = f2tf(kv.z); p[pe(e+3)] = f2tf(kv.w);
            float4 vv = *(const float4*)&Vg[(size_t)(j0+r)*HSZ + c];
            float4 vo = make_float4(f2tf(vv.x), f2tf(vv.y), f2tf(vv.z), f2tf(vv.w));
            *(float4*)&vs[r*ALD + c] = vo;
        }
        __syncthreads();

        // ---- S = Q @ K^T ----
        float sc[2][8][4];
#pragma unroll
        for (int mt = 0; mt < 2; mt++)
#pragma unroll
            for (int nt = 0; nt < 8; nt++)
#pragma unroll
                for (int k = 0; k < 4; k++) sc[mt][nt][k] = 0.f;

#pragma unroll
        for (int u = 0; u < 8; u++) {
            uint32_t qa[2][4];
#pragma unroll
            for (int mt = 0; mt < 2; mt++) {
                int rm = wr + mt*16;
                float2 lo = *(const float2*)&qs[(rm+qr  )*ALD + u*8 + 2*qc];
                float2 hi = *(const float2*)&qs[(rm+qr+8)*ALD + u*8 + 2*qc];
                qa[mt][0] = __float_as_uint(lo.x); qa[mt][1] = __float_as_uint(hi.x);
                qa[mt][2] = __float_as_uint(lo.y); qa[mt][3] = __float_as_uint(hi.y);
            }
#pragma unroll
            for (int nt = 0; nt < 8; nt++) {
                float2 kb = *(const float2*)&ks[(nt*8+qr)*ALD + u*8 + 2*qc];
                uint32_t bb[2] = { __float_as_uint(kb.x), __float_as_uint(kb.y) };
                mma8(sc[0][nt], qa[0], bb);
                mma8(sc[1][nt], qa[1], bb);
            }
        }

        // ---- online softmax + stats (rows: wr+mt*16+qr, +8) ----
#pragma unroll
        for (int mt = 0; mt < 2; mt++) {
#pragma unroll
            for (int hi = 0; hi < 2; hi++) {
                float lm = -1e30f;
#pragma unroll
                for (int nt = 0; nt < 8; nt++) {
                    sc[mt][nt][2*hi  ] *= 0.125f;
                    sc[mt][nt][2*hi+1] *= 0.125f;
                    lm = fmaxf(lm, fmaxf(sc[mt][nt][2*hi], sc[mt][nt][2*hi+1]));
                }
                lm = fmaxf(lm, __shfl_xor_sync(0xffffffffu, lm, 1));
                lm = fmaxf(lm, __shfl_xor_sync(0xffffffffu, lm, 2));
                float mo = m[mt][hi];
                float mn = fmaxf(mo, lm);
                float al = __expf(mo - mn);
                T[mt][hi] = al * (T[mt][hi] + (mo - mn) * Z[mt][hi]);
                Z[mt][hi] *= al;
                E[mt][hi] *= al;
#pragma unroll
                for (int nt = 0; nt < 8; nt++) {
                    O[mt][nt][2*hi  ] *= al;
                    O[mt][nt][2*hi+1] *= al;
                }
                m[mt][hi] = mn;
                float sp = 0.f, st = 0.f, pm = 0.f;
#pragma unroll
                for (int nt = 0; nt < 8; nt++) {
#pragma unroll
                    for (int k = 0; k < 2; k++) {
                        float d = sc[mt][nt][2*hi+k] - mn;
                        float p = __expf(d);
                        sp += p; st += p*d; pm = fmaxf(pm, p);
                        sc[mt][nt][2*hi+k] = p;
                    }
                }
                sp += __shfl_xor_sync(0xffffffffu, sp, 1);
                sp += __shfl_xor_sync(0xffffffffu, sp, 2);
                st += __shfl_xor_sync(0xffffffffu, st, 1);
                st += __shfl_xor_sync(0xffffffffu, st, 2);
                pm  = fmaxf(pm, __shfl_xor_sync(0xffffffffu, pm, 1));
                pm  = fmaxf(pm, __shfl_xor_sync(0xffffffffu, pm, 2));
                Z[mt][hi] += sp; T[mt][hi] += st; E[mt][hi] = fmaxf(E[mt][hi], pm);
            }
        }

        // ---- P -> smem (tf32, j-permuted) ----
#pragma unroll
        for (int mt = 0; mt < 2; mt++) {
            int rm = wr + mt*16;
#pragma unroll
            for (int nt = 0; nt < 8; nt++) {
                int cb = nt*8;
                ps[(rm+qr  )*ALD + cb + pe(2*qc  )] = f2tf(sc[mt][nt][0]);
                ps[(rm+qr  )*ALD + cb + pe(2*qc+1)] = f2tf(sc[mt][nt][1]);
                ps[(rm+qr+8)*ALD + cb + pe(2*qc  )] = f2tf(sc[mt][nt][2]);
                ps[(rm+qr+8)*ALD + cb + pe(2*qc+1)] = f2tf(sc[mt][nt][3]);
            }
        }
        __syncthreads();

        // ---- O += P @ V ----
#pragma unroll
        for (int u = 0; u < 8; u++) {
            uint32_t pa[2][4];
#pragma unroll
            for (int mt = 0; mt < 2; mt++) {
                int rm = wr + mt*16;
                float2 lo = *(const float2*)&ps[(rm+qr  )*ALD + u*8 + 2*qc];
                float2 hi = *(const float2*)&ps[(rm+qr+8)*ALD + u*8 + 2*qc];
                pa[mt][0] = __float_as_uint(lo.x); pa[mt][1] = __float_as_uint(hi.x);
                pa[mt][2] = __float_as_uint(lo.y); pa[mt][3] = __float_as_uint(hi.y);
            }
#pragma unroll
            for (int nt = 0; nt < 8; nt++) {
                uint32_t bb[2];
                bb[0] = __float_as_uint(vs[(u*8+qc  )*ALD + nt*8+qr]);
                bb[1] = __float_as_uint(vs[(u*8+qc+4)*ALD + nt*8+qr]);
                mma8(O[0][nt], pa[0], bb);
                mma8(O[1][nt], pa[1], bb);
            }
        }
    }

    // ---- epilogue: normalize, write context + per-row stats ----
#pragma unroll
    for (int mt = 0; mt < 2; mt++) {
        int rml = wr + mt*16;
#pragma unroll
        for (int hi = 0; hi < 2; hi++) {
            int row = rml + qr + 8*hi;
            float iz = 1.0f / Z[mt][hi];
#pragma unroll
            for (int nt = 0; nt < 8; nt++) {
                float2 o;
                o.x = O[mt][nt][2*hi  ] * iz;
                o.y = O[mt][nt][2*hi+1] * iz;
                *(float2*)&ctx[((size_t)(b*SEQ + q0 + row))*HSZ + h*HDM + nt*8 + 2*qc] = o;
            }
            if (qc == 0) {
                int idx = bh*SEQ + q0 + row;
                g_ent[idx] = logf(Z[mt][hi]) - T[mt][hi]*iz;
                g_mxp[idx] = E[mt][hi]*iz;
            }
        }
    }
}

// ===========================================================================
// Deterministic final reduction: 3 scalar means (no atomics).
// ===========================================================================
__global__ void reduce_kernel(float* __restrict__ out, int n_ctx)
{
    __shared__ float se[512], si[512], sc[512];
    int t = threadIdx.x;
    float e = 0.f, i = 0.f, c = 0.f;
    for (int l = t; l < NSTAT; l += 512) {
        e += g_ent[l];
        i += fabsf(g_gov[l]);
        c += g_mxp[l];
    }
    se[t] = e; si[t] = i; sc[t] = c;
    __syncthreads();
    for (int s2 = 256; s2 > 0; s2 >>= 1) {
        if (t < s2) { se[t] += se[t+s2]; si[t] += si[t+s2]; sc[t] += sc[t+s2]; }
        __syncthreads();
    }
    if (t == 0) {
        const float inv = 1.0f / (float)NSTAT;
        out[n_ctx + 0] = se[0] * inv;
        out[n_ctx + 1] = si[0] * inv;
        out[n_ctx + 2] = sc[0] * inv;
    }
}

// ===========================================================================
extern "C" void kernel_launch(void* const* d_in, const int* in_sizes, int n_in,
                              void* d_out, int out_size)
{
    const float* X   = (const float*)d_in[0];
    const float* GE  = (const float*)d_in[1];
    const float* Wq  = (const float*)d_in[2];  const float* bq  = (const float*)d_in[3];
    const float* Wk  = (const float*)d_in[4];  const float* bk  = (const float*)d_in[5];
    const float* Wv  = (const float*)d_in[6];  const float* bv  = (const float*)d_in[7];
    const float* Wgq = (const float*)d_in[8];  const float* bgq = (const float*)d_in[9];
    const float* Wgk = (const float*)d_in[10]; const float* bgk = (const float*)d_in[11];
    float* out = (float*)d_out;

    cudaFuncSetAttribute(attn_kernel, cudaFuncAttributeMaxDynamicSharedMemorySize, ATT_SMEM);

    proj_kernel<<<dim3(8, 32, 4), 256>>>(X, Wq, bq, Wk, bk, Wv, bv, Wgk, bgk);
    gq_kernel<<<dim3(4, 2), 256>>>(GE, Wgq, bgq);
    gov_kernel<<<NSTAT*32/256, 256>>>();
    attn_kernel<<<dim3(SEQ/128, BSZ*NHD), 128, ATT_SMEM>>>(out);
    reduce_kernel<<<1, 512>>>(out, out_size - 3);
}